// round 4
// baseline (speedup 1.0000x reference)
#include <cuda_runtime.h>
#include <cuda_bf16.h>
#include <math.h>
#include <stdint.h>

#define LSEQ   2048
#define BATCH  4
#define NT     8192          // BATCH * LSEQ
#define CDIM   256
#define DIN    512
#define DSTATE 16
#define DTRANK 16
#define NCHUNK 32
#define CHLEN  64            // LSEQ / NCHUNK

// ---------------- scratch (static __device__, no allocs) ----------------
__device__ __nv_bfloat16 g_u_h [NT * CDIM];    // 4 MB (B*L, C) ln output hi
__device__ __nv_bfloat16 g_u_l [NT * CDIM];    // 4 MB lo
__device__ __nv_bfloat16 g_wih [2*DIN * CDIM]; // in_proj_w hi  (1024,256)
__device__ __nv_bfloat16 g_wil [2*DIN * CDIM];
__device__ __nv_bfloat16 g_woh [CDIM * DIN];   // out_proj_w hi (256,512)
__device__ __nv_bfloat16 g_wol [CDIM * DIN];
__device__ float g_xz   [2 * DIN * NT];        // 32 MB (2*DIN, B*L) in_proj out
__device__ float g_xc   [DIN * NT];            // 16 MB (DIN, B*L) conv+silu
__device__ float g_xpart[4 * 48 * NT];         //  6 MB x_proj split-K partials
__device__ float g_dtarr[NT * DTRANK];         // (B*L, 16)
__device__ float g_Bm   [NT * DSTATE];         // (B*L, 16)
__device__ float g_Cm   [NT * DSTATE];         // (B*L, 16)
__device__ __nv_bfloat16 g_y_h [NT * DIN];     // 8 MB (B*L, DIN) gated y hi
__device__ __nv_bfloat16 g_y_l [NT * DIN];     // 8 MB lo
__device__ float g_op   [CDIM * NT];           //  8 MB (C, B*L) out_proj out
__device__ float g_P    [BATCH * NCHUNK * DIN * DSTATE];
__device__ float g_q    [BATCH * NCHUNK * DIN * DSTATE];
__device__ float g_h0   [BATCH * NCHUNK * DIN * DSTATE];

__device__ __forceinline__ uint32_t s2u(const void* p) {
    return (uint32_t)__cvta_generic_to_shared(p);
}
__device__ __forceinline__ void ldsm4(uint32_t* r, uint32_t addr) {
    asm volatile("ldmatrix.sync.aligned.m8n8.x4.shared.b16 {%0,%1,%2,%3}, [%4];"
        : "=r"(r[0]), "=r"(r[1]), "=r"(r[2]), "=r"(r[3]) : "r"(addr));
}
__device__ __forceinline__ void mma16816(float* c, const uint32_t* a, uint32_t b0, uint32_t b1) {
    asm volatile("mma.sync.aligned.m16n8k16.row.col.f32.bf16.bf16.f32 "
        "{%0,%1,%2,%3}, {%4,%5,%6,%7}, {%8,%9}, {%0,%1,%2,%3};"
        : "+f"(c[0]), "+f"(c[1]), "+f"(c[2]), "+f"(c[3])
        : "r"(a[0]), "r"(a[1]), "r"(a[2]), "r"(a[3]), "r"(b0), "r"(b1));
}
__device__ __forceinline__ void cpasync16(void* smem, const void* gptr) {
    asm volatile("cp.async.cg.shared.global [%0], [%1], 16;"
        :: "r"(s2u(smem)), "l"(gptr));
}
__device__ __forceinline__ void cpcommit() { asm volatile("cp.async.commit_group;"); }

// ---------------- K0: fp32 -> bf16 hi/lo conversion (weights) ---------------
__global__ void cvt_kernel(const float* __restrict__ src,
                           __nv_bfloat16* __restrict__ dh,
                           __nv_bfloat16* __restrict__ dl, int n) {
    int i = blockIdx.x * 256 + threadIdx.x;
    if (i < n) {
        float v = src[i];
        __nv_bfloat16 h = __float2bfloat16(v);
        dh[i] = h;
        dl[i] = __float2bfloat16(v - __bfloat162float(h));
    }
}

// ---------------- K1: input LayerNorm (over C), emit bf16 hi/lo (NT, C) -----
__global__ void ln_in_kernel(const float* __restrict__ x,
                             const float* __restrict__ w,
                             const float* __restrict__ bias) {
    int b  = blockIdx.y;
    int tid = threadIdx.x;
    int lx = tid & 31;
    int ty = tid >> 5;
    int l0 = blockIdx.x * 32;
    __shared__ float T[CDIM][33];
    __shared__ float sS[8][32], sQ[8][32], sMean[32], sR[32];

    const float* xb = x + (size_t)b * CDIM * LSEQ + l0 + lx;
    float s = 0.f, q = 0.f;
    for (int c = ty; c < CDIM; c += 8) {
        float v = xb[(size_t)c * LSEQ];
        T[c][lx] = v;
        s += v; q += v * v;
    }
    sS[ty][lx] = s; sQ[ty][lx] = q;
    __syncthreads();
    if (ty == 0) {
        float ts = 0.f, tq = 0.f;
        #pragma unroll
        for (int i = 0; i < 8; i++) { ts += sS[i][lx]; tq += sQ[i][lx]; }
        float m   = ts * (1.f / CDIM);
        float var = tq * (1.f / CDIM) - m * m;
        sMean[lx] = m;
        sR[lx]    = rsqrtf(var + 1e-5f);
    }
    __syncthreads();
    int c = tid;
    float wc = w[c], bc = bias[c];
    #pragma unroll 4
    for (int l = 0; l < 32; l++) {
        float v = (T[c][l] - sMean[l]) * sR[l] * wc + bc;
        __nv_bfloat16 h = __float2bfloat16(v);
        size_t idx = (size_t)(b * LSEQ + l0 + l) * CDIM + c;
        g_u_h[idx] = h;
        g_u_l[idx] = __float2bfloat16(v - __bfloat162float(h));
    }
}

// ---------------- K2: bf16 hi/lo TN GEMM, cp.async double-buffered ----------
// C[M,N] = A[M,K]*Bn[N,K]^T (3-term hi/lo). BM=128 BN=128 BK=32.
// 8 warps 2(m)x4(n), warp tile 64x32.
__global__ __launch_bounds__(256, 2)
void gemm_bf16_kernel(const __nv_bfloat16* __restrict__ Ahp,
                      const __nv_bfloat16* __restrict__ Alp,
                      const __nv_bfloat16* __restrict__ Bhp,
                      const __nv_bfloat16* __restrict__ Blp,
                      float* __restrict__ C, int M, int N, int K) {
    __shared__ __nv_bfloat16 sAh[2][128][40], sAl[2][128][40];
    __shared__ __nv_bfloat16 sBh[2][128][40], sBl[2][128][40];
    const int tid = threadIdx.x, lane = tid & 31, wid = tid >> 5;
    const int m0 = blockIdx.y * 128, n0 = blockIdx.x * 128;
    const int wm = (wid & 1) * 64;
    const int wn = (wid >> 1) * 32;
    const int lr = lane & 15;
    const int lc = (lane & 16) ? 8 : 0;

    const int grow = tid >> 2;           // 0..63 (two rows per thread: grow, grow+64)
    const int gcol = (tid & 3) * 8;      // bf16 col: 0,8,16,24

    float acc[4][4][4];
    #pragma unroll
    for (int mi = 0; mi < 4; mi++)
        #pragma unroll
        for (int nf = 0; nf < 4; nf++)
            #pragma unroll
            for (int e = 0; e < 4; e++) acc[mi][nf][e] = 0.f;

    const int nk = K >> 5;

    // load slab kt into buffer buf
    auto load_slab = [&](int kt, int buf) {
        int k0 = kt * 32;
        #pragma unroll
        for (int h = 0; h < 2; h++) {
            int r = grow + h * 64;
            cpasync16(&sAh[buf][r][gcol], Ahp + (size_t)(m0 + r) * K + k0 + gcol);
            cpasync16(&sAl[buf][r][gcol], Alp + (size_t)(m0 + r) * K + k0 + gcol);
            cpasync16(&sBh[buf][r][gcol], Bhp + (size_t)(n0 + r) * K + k0 + gcol);
            cpasync16(&sBl[buf][r][gcol], Blp + (size_t)(n0 + r) * K + k0 + gcol);
        }
        cpcommit();
    };

    load_slab(0, 0);
    for (int kt = 0; kt < nk; kt++) {
        const int buf = kt & 1;
        if (kt + 1 < nk) {
            load_slab(kt + 1, buf ^ 1);
            asm volatile("cp.async.wait_group 1;");
        } else {
            asm volatile("cp.async.wait_group 0;");
        }
        __syncthreads();
        #pragma unroll
        for (int kk = 0; kk < 2; kk++) {
            const int k16 = kk * 16;
            uint32_t ah[4][4], al[4][4];
            #pragma unroll
            for (int mi = 0; mi < 4; mi++) {
                ldsm4(ah[mi], s2u(&sAh[buf][wm + mi * 16 + lr][k16 + lc]));
                ldsm4(al[mi], s2u(&sAl[buf][wm + mi * 16 + lr][k16 + lc]));
            }
            #pragma unroll
            for (int nj = 0; nj < 2; nj++) {
                uint32_t bh[4], bl[4];
                ldsm4(bh, s2u(&sBh[buf][wn + nj * 16 + lr][k16 + lc]));
                ldsm4(bl, s2u(&sBl[buf][wn + nj * 16 + lr][k16 + lc]));
                #pragma unroll
                for (int sub = 0; sub < 2; sub++) {
                    int nf = nj * 2 + sub;
                    #pragma unroll
                    for (int mi = 0; mi < 4; mi++) {
                        mma16816(acc[mi][nf], ah[mi], bh[sub], bh[sub + 2]);
                        mma16816(acc[mi][nf], ah[mi], bl[sub], bl[sub + 2]);
                        mma16816(acc[mi][nf], al[mi], bh[sub], bh[sub + 2]);
                    }
                }
            }
        }
        __syncthreads();
    }

    #pragma unroll
    for (int mi = 0; mi < 4; mi++)
        #pragma unroll
        for (int nf = 0; nf < 4; nf++) {
            int row = m0 + wm + mi * 16 + (lane >> 2);
            int col = n0 + wn + nf * 8 + ((lane & 3) << 1);
            float2 v0; v0.x = acc[mi][nf][0]; v0.y = acc[mi][nf][1];
            float2 v1; v1.x = acc[mi][nf][2]; v1.y = acc[mi][nf][3];
            *(float2*)&C[(size_t)row * N + col]       = v0;
            *(float2*)&C[(size_t)(row + 8) * N + col] = v1;
        }
}

// ---------------- K3: causal depthwise conv (width 4) + SiLU ----------------
__global__ void conv_kernel(const float* __restrict__ cw,
                            const float* __restrict__ cb) {
    int d = blockIdx.y;
    int n = blockIdx.x * 256 + threadIdx.x;
    const float* xin = g_xz + (size_t)d * NT;
    float w0 = cw[d * 4 + 0], w1 = cw[d * 4 + 1];
    float w2 = cw[d * 4 + 2], w3 = cw[d * 4 + 3];
    int l = n & (LSEQ - 1);
    float v = cb[d] + w3 * xin[n];
    if (l >= 1) v = fmaf(w2, xin[n - 1], v);
    if (l >= 2) v = fmaf(w1, xin[n - 2], v);
    if (l >= 3) v = fmaf(w0, xin[n - 3], v);
    v = v / (1.f + __expf(-v));          // SiLU
    g_xc[(size_t)d * NT + n] = v;
}

// ---------------- K4a: x_proj split-K partials ------------------------------
// grid (NT/64, 4): block computes (48 x 64) over its 128-d slice.
__global__ void xproj_part_kernel(const float* __restrict__ W) {
    __shared__ float Ws[48][64];
    __shared__ float Xs[64][68];
    int t  = threadIdx.x;
    int n0 = blockIdx.x * 64;
    int ks = blockIdx.y;
    int tn = t & 63, tk = t >> 6;
    float acc[12];
    #pragma unroll
    for (int j = 0; j < 12; j++) acc[j] = 0.f;

    for (int cc = 0; cc < 2; cc++) {
        int d0 = ks * 128 + cc * 64;
        __syncthreads();
        for (int i = t; i < 768; i += 256) {
            int r = i >> 4, c4 = (i & 15) << 2;
            *(float4*)&Ws[r][c4] = *(const float4*)&W[(size_t)r * DIN + d0 + c4];
        }
        for (int i = t; i < 1024; i += 256) {
            int r = i >> 4, c4 = (i & 15) << 2;
            *(float4*)&Xs[r][c4] = *(const float4*)&g_xc[(size_t)(d0 + r) * NT + n0 + c4];
        }
        __syncthreads();
        #pragma unroll 4
        for (int dd = 0; dd < 64; dd++) {
            float xv = Xs[dd][tn];
            #pragma unroll
            for (int j = 0; j < 12; j++)
                acc[j] = fmaf(xv, Ws[tk * 12 + j][dd], acc[j]);
        }
    }
    int n = n0 + tn;
    #pragma unroll
    for (int j = 0; j < 12; j++) {
        int k = tk * 12 + j;
        g_xpart[((size_t)ks * 48 + k) * NT + n] = acc[j];
    }
}

// ---------------- K4b: reduce partials -> dt/Bm/Cm in (n,16) layout ---------
__global__ void xred_kernel() {
    int idx = blockIdx.x * 256 + threadIdx.x;       // 48 * NT
    int k = idx / NT, n = idx - k * NT;
    float s = g_xpart[(size_t)k * NT + n]
            + g_xpart[((size_t)48 + k) * NT + n]
            + g_xpart[((size_t)96 + k) * NT + n]
            + g_xpart[((size_t)144 + k) * NT + n];
    if (k < DTRANK)                g_dtarr[(size_t)n * 16 + k] = s;
    else if (k < DTRANK + DSTATE)  g_Bm[(size_t)n * 16 + (k - DTRANK)] = s;
    else                           g_Cm[(size_t)n * 16 + (k - DTRANK - DSTATE)] = s;
}

// ---------------- K5a: chunk scan pass1 (delta fused via shuffle) -----------
__global__ void scan_p1_kernel(const float* __restrict__ Alog,
                               const float* __restrict__ dtw,
                               const float* __restrict__ dtb) {
    int b  = blockIdx.z;
    int ch = blockIdx.y;
    int g  = threadIdx.x >> 4;
    int nl = threadIdx.x & 15;
    int d  = blockIdx.x * 16 + g;

    float Adn = -__expf(Alog[d * DSTATE + nl]);
    float wdt = dtw[d * DTRANK + nl];
    float bdt = dtb[d];
    float P = 1.f, q = 0.f;
    int base = b * LSEQ + ch * CHLEN;
    const float* xcrow = g_xc + (size_t)d * NT + base;
    const float* dtp = g_dtarr + (size_t)base * 16;
    const float* Bp  = g_Bm + (size_t)base * 16;

    #pragma unroll 4
    for (int l = 0; l < CHLEN; l++) {
        float s = dtp[l * 16 + nl] * wdt;
        s += __shfl_xor_sync(0xffffffffu, s, 1);
        s += __shfl_xor_sync(0xffffffffu, s, 2);
        s += __shfl_xor_sync(0xffffffffu, s, 4);
        s += __shfl_xor_sync(0xffffffffu, s, 8);
        s += bdt;
        float delta = (s > 20.f) ? s : log1pf(__expf(s));
        float dA = __expf(delta * Adn);
        q = fmaf(dA, q, delta * Bp[l * 16 + nl] * xcrow[l]);
        P *= dA;
    }
    size_t idx = ((size_t)(b * NCHUNK + ch) * DIN + d) * 16 + nl;
    g_P[idx] = P;
    g_q[idx] = q;
}

// ---------------- K5b: prefix over chunks -> h0 -----------------------------
__global__ void scan_p2_kernel() {
    int idx = blockIdx.x * 256 + threadIdx.x;
    int n = idx & 15;
    int d = (idx >> 4) & (DIN - 1);
    int b = idx >> 13;
    float h = 0.f;
    #pragma unroll
    for (int ch = 0; ch < NCHUNK; ch++) {
        size_t p = ((size_t)(b * NCHUNK + ch) * DIN + d) * 16 + n;
        g_h0[p] = h;
        h = fmaf(g_P[p], h, g_q[p]);
    }
}

// ---------------- K5c: replay + y + gating, emit y bf16 hi/lo (NT, DIN) -----
__global__ void scan_p3_kernel(const float* __restrict__ Alog,
                               const float* __restrict__ dtw,
                               const float* __restrict__ dtb,
                               const float* __restrict__ Dp) {
    int b  = blockIdx.z;
    int ch = blockIdx.y;
    int g  = threadIdx.x >> 4;
    int nl = threadIdx.x & 15;
    int d  = blockIdx.x * 16 + g;

    float Adn = -__expf(Alog[d * DSTATE + nl]);
    float wdt = dtw[d * DTRANK + nl];
    float bdt = dtb[d];
    float Dd  = Dp[d];
    float h = g_h0[((size_t)(b * NCHUNK + ch) * DIN + d) * 16 + nl];

    int base = b * LSEQ + ch * CHLEN;
    const float* xcrow = g_xc + (size_t)d * NT + base;
    const float* zrow  = g_xz + (size_t)(DIN + d) * NT + base;
    const float* dtp = g_dtarr + (size_t)base * 16;
    const float* Bp = g_Bm + (size_t)base * 16;
    const float* Cp = g_Cm + (size_t)base * 16;

    #pragma unroll 4
    for (int l = 0; l < CHLEN; l++) {
        float s = dtp[l * 16 + nl] * wdt;
        s += __shfl_xor_sync(0xffffffffu, s, 1);
        s += __shfl_xor_sync(0xffffffffu, s, 2);
        s += __shfl_xor_sync(0xffffffffu, s, 4);
        s += __shfl_xor_sync(0xffffffffu, s, 8);
        s += bdt;
        float delta = (s > 20.f) ? s : log1pf(__expf(s));
        float xcv = xcrow[l];
        float dA = __expf(delta * Adn);
        h = fmaf(dA, h, delta * Bp[l * 16 + nl] * xcv);
        float yv = h * Cp[l * 16 + nl];
        yv += __shfl_xor_sync(0xffffffffu, yv, 1);
        yv += __shfl_xor_sync(0xffffffffu, yv, 2);
        yv += __shfl_xor_sync(0xffffffffu, yv, 4);
        yv += __shfl_xor_sync(0xffffffffu, yv, 8);
        if (nl == 0) {
            float zl = zrow[l];
            float silu = zl / (1.f + __expf(-zl));
            float out = (yv + Dd * xcv) * silu;
            __nv_bfloat16 hh = __float2bfloat16(out);
            size_t yi = (size_t)(base + l) * DIN + d;
            g_y_h[yi] = hh;
            g_y_l[yi] = __float2bfloat16(out - __bfloat162float(hh));
        }
    }
}

// ---------------- K6: residual + output LayerNorm, write (B,C,L,1) ----------
__global__ void ln_out_kernel(const float* __restrict__ x,
                              const float* __restrict__ w,
                              const float* __restrict__ bias,
                              float* __restrict__ out) {
    int b  = blockIdx.y;
    int lx = threadIdx.x;
    int ty = threadIdx.y;
    int l  = blockIdx.x * 32 + lx;
    __shared__ float sS[8][32], sQ[8][32], sMean[32], sR[32];

    const float* xb = x + (size_t)b * CDIM * LSEQ + l;
    const float* ob = g_op + (size_t)b * LSEQ + l;
    float s = 0.f, q = 0.f;
    for (int c = ty; c < CDIM; c += 8) {
        float v = ob[(size_t)c * NT] + xb[(size_t)c * LSEQ];
        s += v; q += v * v;
    }
    sS[ty][lx] = s; sQ[ty][lx] = q;
    __syncthreads();
    if (ty == 0) {
        float ts = 0.f, tq = 0.f;
        #pragma unroll
        for (int i = 0; i < 8; i++) { ts += sS[i][lx]; tq += sQ[i][lx]; }
        float m   = ts * (1.f / CDIM);
        float var = tq * (1.f / CDIM) - m * m;
        sMean[lx] = m;
        sR[lx]    = rsqrtf(var + 1e-5f);
    }
    __syncthreads();
    float m = sMean[lx], r = sR[lx];
    float* outb = out + (size_t)b * CDIM * LSEQ + l;
    for (int c = ty; c < CDIM; c += 8) {
        float v = ob[(size_t)c * NT] + xb[(size_t)c * LSEQ];
        outb[(size_t)c * LSEQ] = (v - m) * r * w[c] + bias[c];
    }
}

// ---------------- launch -----------------------------------------------------
extern "C" void kernel_launch(void* const* d_in, const int* in_sizes, int n_in,
                              void* d_out, int out_size) {
    const float* x         = (const float*)d_in[0];
    const float* ln_w      = (const float*)d_in[1];
    const float* ln_b      = (const float*)d_in[2];
    const float* in_proj_w = (const float*)d_in[3];
    const float* conv_w    = (const float*)d_in[4];
    const float* conv_b    = (const float*)d_in[5];
    const float* x_proj_w  = (const float*)d_in[6];
    const float* dt_proj_w = (const float*)d_in[7];
    const float* dt_proj_b = (const float*)d_in[8];
    const float* A_log     = (const float*)d_in[9];
    const float* Dv        = (const float*)d_in[10];
    const float* out_proj_w= (const float*)d_in[11];
    float* out = (float*)d_out;

    __nv_bfloat16 *p_uh, *p_ul, *p_wih, *p_wil, *p_woh, *p_wol, *p_yh, *p_yl;
    float *p_xz, *p_op;
    cudaGetSymbolAddress((void**)&p_uh,  g_u_h);
    cudaGetSymbolAddress((void**)&p_ul,  g_u_l);
    cudaGetSymbolAddress((void**)&p_wih, g_wih);
    cudaGetSymbolAddress((void**)&p_wil, g_wil);
    cudaGetSymbolAddress((void**)&p_woh, g_woh);
    cudaGetSymbolAddress((void**)&p_wol, g_wol);
    cudaGetSymbolAddress((void**)&p_yh,  g_y_h);
    cudaGetSymbolAddress((void**)&p_yl,  g_y_l);
    cudaGetSymbolAddress((void**)&p_xz,  g_xz);
    cudaGetSymbolAddress((void**)&p_op,  g_op);

    cvt_kernel<<<(2 * DIN * CDIM) / 256, 256>>>(in_proj_w, p_wih, p_wil, 2 * DIN * CDIM);
    cvt_kernel<<<(CDIM * DIN) / 256, 256>>>(out_proj_w, p_woh, p_wol, CDIM * DIN);

    ln_in_kernel<<<dim3(LSEQ / 32, BATCH), 256>>>(x, ln_w, ln_b);

    // in_proj: (1024,256) @ (8192,256)^T
    gemm_bf16_kernel<<<dim3(NT / 128, (2 * DIN) / 128), 256>>>(
        p_wih, p_wil, p_uh, p_ul, p_xz, 2 * DIN, NT, CDIM);

    conv_kernel<<<dim3(NT / 256, DIN), 256>>>(conv_w, conv_b);

    xproj_part_kernel<<<dim3(NT / 64, 4), 256>>>(x_proj_w);
    xred_kernel<<<(48 * NT) / 256, 256>>>();

    scan_p1_kernel<<<dim3(DIN / 16, NCHUNK, BATCH), 256>>>(A_log, dt_proj_w, dt_proj_b);
    scan_p2_kernel<<<dim3(BATCH * DIN * 16 / 256), 256>>>();
    scan_p3_kernel<<<dim3(DIN / 16, NCHUNK, BATCH), 256>>>(A_log, dt_proj_w, dt_proj_b, Dv);

    // out_proj: (256,512) @ (8192,512)^T
    gemm_bf16_kernel<<<dim3(NT / 128, CDIM / 128), 256>>>(
        p_woh, p_wol, p_yh, p_yl, p_op, CDIM, NT, DIN);

    ln_out_kernel<<<dim3(LSEQ / 32, BATCH), dim3(32, 8)>>>(x, ln_w, ln_b, out);
}

// round 5
// speedup vs baseline: 1.0080x; 1.0080x over previous
#include <cuda_runtime.h>
#include <cuda_bf16.h>
#include <math.h>
#include <stdint.h>

#define LSEQ   2048
#define BATCH  4
#define NT     8192          // BATCH * LSEQ
#define CDIM   256
#define DIN    512
#define DSTATE 16
#define DTRANK 16
#define NCHUNK 32
#define CHLEN  64            // LSEQ / NCHUNK

// ---------------- scratch (static __device__, no allocs) ----------------
__device__ __nv_bfloat16 g_u_h [NT * CDIM];    // ln output hi (B*L, C)
__device__ __nv_bfloat16 g_u_l [NT * CDIM];
__device__ __nv_bfloat16 g_wih [2*DIN * CDIM]; // in_proj_w hi/lo (1024,256)
__device__ __nv_bfloat16 g_wil [2*DIN * CDIM];
__device__ __nv_bfloat16 g_woh [CDIM * DIN];   // out_proj_w hi/lo (256,512)
__device__ __nv_bfloat16 g_wol [CDIM * DIN];
__device__ float g_xz   [2 * DIN * NT];        // (2*DIN, B*L) in_proj out
__device__ float g_xpart[4 * 48 * NT];         // x_proj split-K partials
__device__ float g_dtarr[NT * DTRANK];         // (B*L, 16)
__device__ float g_Bm   [NT * DSTATE];         // (B*L, 16)
__device__ float g_Cm   [NT * DSTATE];         // (B*L, 16)
__device__ float g_delta[DIN * NT];            // (DIN, B*L) softplus(dt_proj)
__device__ __nv_bfloat16 g_y_h [NT * DIN];     // (B*L, DIN) gated y hi/lo
__device__ __nv_bfloat16 g_y_l [NT * DIN];
__device__ float g_op   [CDIM * NT];           // (C, B*L) out_proj out
__device__ float g_P    [BATCH * NCHUNK * DIN * DSTATE];
__device__ float g_q    [BATCH * NCHUNK * DIN * DSTATE];
__device__ float g_h0   [BATCH * NCHUNK * DIN * DSTATE];

__device__ __forceinline__ uint32_t s2u(const void* p) {
    return (uint32_t)__cvta_generic_to_shared(p);
}
__device__ __forceinline__ void ldsm4(uint32_t* r, uint32_t addr) {
    asm volatile("ldmatrix.sync.aligned.m8n8.x4.shared.b16 {%0,%1,%2,%3}, [%4];"
        : "=r"(r[0]), "=r"(r[1]), "=r"(r[2]), "=r"(r[3]) : "r"(addr));
}
__device__ __forceinline__ void mma16816(float* c, const uint32_t* a, uint32_t b0, uint32_t b1) {
    asm volatile("mma.sync.aligned.m16n8k16.row.col.f32.bf16.bf16.f32 "
        "{%0,%1,%2,%3}, {%4,%5,%6,%7}, {%8,%9}, {%0,%1,%2,%3};"
        : "+f"(c[0]), "+f"(c[1]), "+f"(c[2]), "+f"(c[3])
        : "r"(a[0]), "r"(a[1]), "r"(a[2]), "r"(a[3]), "r"(b0), "r"(b1));
}
__device__ __forceinline__ void cpasync16(void* smem, const void* gptr) {
    asm volatile("cp.async.cg.shared.global [%0], [%1], 16;"
        :: "r"(s2u(smem)), "l"(gptr));
}

// ---------------- K0: fp32 -> bf16 hi/lo (both weight matrices) -------------
__global__ void cvt_kernel(const float* __restrict__ wi,
                           const float* __restrict__ wo) {
    int i = blockIdx.x * 256 + threadIdx.x;
    const int n1 = 2 * DIN * CDIM;
    if (i < n1) {
        float v = wi[i];
        __nv_bfloat16 h = __float2bfloat16(v);
        g_wih[i] = h;
        g_wil[i] = __float2bfloat16(v - __bfloat162float(h));
    } else {
        int j = i - n1;
        float v = wo[j];
        __nv_bfloat16 h = __float2bfloat16(v);
        g_woh[j] = h;
        g_wol[j] = __float2bfloat16(v - __bfloat162float(h));
    }
}

// ---------------- K1: input LayerNorm (over C), emit bf16 hi/lo (NT, C) -----
__global__ void ln_in_kernel(const float* __restrict__ x,
                             const float* __restrict__ w,
                             const float* __restrict__ bias) {
    int b  = blockIdx.y;
    int tid = threadIdx.x;
    int lx = tid & 31;
    int ty = tid >> 5;
    int l0 = blockIdx.x * 32;
    __shared__ float T[CDIM][33];
    __shared__ float sS[8][32], sQ[8][32], sMean[32], sR[32];

    const float* xb = x + (size_t)b * CDIM * LSEQ + l0 + lx;
    float s = 0.f, q = 0.f;
    for (int c = ty; c < CDIM; c += 8) {
        float v = xb[(size_t)c * LSEQ];
        T[c][lx] = v;
        s += v; q += v * v;
    }
    sS[ty][lx] = s; sQ[ty][lx] = q;
    __syncthreads();
    if (ty == 0) {
        float ts = 0.f, tq = 0.f;
        #pragma unroll
        for (int i = 0; i < 8; i++) { ts += sS[i][lx]; tq += sQ[i][lx]; }
        float m   = ts * (1.f / CDIM);
        float var = tq * (1.f / CDIM) - m * m;
        sMean[lx] = m;
        sR[lx]    = rsqrtf(var + 1e-5f);
    }
    __syncthreads();
    int c = tid;
    float wc = w[c], bc = bias[c];
    #pragma unroll 4
    for (int l = 0; l < 32; l++) {
        float v = (T[c][l] - sMean[l]) * sR[l] * wc + bc;
        __nv_bfloat16 h = __float2bfloat16(v);
        size_t idx = (size_t)(b * LSEQ + l0 + l) * CDIM + c;
        g_u_h[idx] = h;
        g_u_l[idx] = __float2bfloat16(v - __bfloat162float(h));
    }
}

// ---------------- K2: bf16 hi/lo TN GEMM, BM128/BN64, cp.async 2-stage ------
// C[M,N] = A[M,K]*Bn[N,K]^T (3-term hi/lo). 8 warps 4(m)x2(n), warp 32x32.
__global__ __launch_bounds__(256, 2)
void gemm_bf16_kernel(const __nv_bfloat16* __restrict__ Ahp,
                      const __nv_bfloat16* __restrict__ Alp,
                      const __nv_bfloat16* __restrict__ Bhp,
                      const __nv_bfloat16* __restrict__ Blp,
                      float* __restrict__ C, int M, int N, int K) {
    __shared__ __nv_bfloat16 sAh[2][128][40], sAl[2][128][40];
    __shared__ __nv_bfloat16 sBh[2][64][40],  sBl[2][64][40];
    const int tid = threadIdx.x, lane = tid & 31, wid = tid >> 5;
    const int m0 = blockIdx.y * 128, n0 = blockIdx.x * 64;
    const int wm = (wid & 3) * 32;
    const int wn = (wid >> 2) * 32;
    const int lr = lane & 15;
    const int lc = (lane & 16) ? 8 : 0;

    const int ar = tid >> 1;             // A row 0..127
    const int ac = (tid & 1) * 8;        // A bf16 col 0 or 8 (+16 second chunk)
    const int br = tid >> 2;             // B row 0..63
    const int bc = (tid & 3) * 8;        // B bf16 col

    float acc[2][4][4];
    #pragma unroll
    for (int mi = 0; mi < 2; mi++)
        #pragma unroll
        for (int nf = 0; nf < 4; nf++)
            #pragma unroll
            for (int e = 0; e < 4; e++) acc[mi][nf][e] = 0.f;

    const int nk = K >> 5;

    auto load_slab = [&](int kt, int buf) {
        int k0 = kt * 32;
        const __nv_bfloat16* Ah0 = Ahp + (size_t)(m0 + ar) * K + k0 + ac;
        const __nv_bfloat16* Al0 = Alp + (size_t)(m0 + ar) * K + k0 + ac;
        cpasync16(&sAh[buf][ar][ac],      Ah0);
        cpasync16(&sAh[buf][ar][ac + 16], Ah0 + 16);
        cpasync16(&sAl[buf][ar][ac],      Al0);
        cpasync16(&sAl[buf][ar][ac + 16], Al0 + 16);
        cpasync16(&sBh[buf][br][bc], Bhp + (size_t)(n0 + br) * K + k0 + bc);
        cpasync16(&sBl[buf][br][bc], Blp + (size_t)(n0 + br) * K + k0 + bc);
        asm volatile("cp.async.commit_group;");
    };

    load_slab(0, 0);
    for (int kt = 0; kt < nk; kt++) {
        const int buf = kt & 1;
        if (kt + 1 < nk) {
            load_slab(kt + 1, buf ^ 1);
            asm volatile("cp.async.wait_group 1;");
        } else {
            asm volatile("cp.async.wait_group 0;");
        }
        __syncthreads();
        #pragma unroll
        for (int kk = 0; kk < 2; kk++) {
            const int k16 = kk * 16;
            uint32_t ah[2][4], al[2][4], bh[2][4], bl[2][4];
            #pragma unroll
            for (int mi = 0; mi < 2; mi++) {
                ldsm4(ah[mi], s2u(&sAh[buf][wm + mi * 16 + lr][k16 + lc]));
                ldsm4(al[mi], s2u(&sAl[buf][wm + mi * 16 + lr][k16 + lc]));
            }
            #pragma unroll
            for (int nj = 0; nj < 2; nj++) {
                ldsm4(bh[nj], s2u(&sBh[buf][wn + nj * 16 + lr][k16 + lc]));
                ldsm4(bl[nj], s2u(&sBl[buf][wn + nj * 16 + lr][k16 + lc]));
            }
            #pragma unroll
            for (int mi = 0; mi < 2; mi++)
                #pragma unroll
                for (int nf = 0; nf < 4; nf++) {
                    int nj = nf >> 1, sub = nf & 1;
                    mma16816(acc[mi][nf], ah[mi], bh[nj][sub], bh[nj][sub + 2]);
                    mma16816(acc[mi][nf], ah[mi], bl[nj][sub], bl[nj][sub + 2]);
                    mma16816(acc[mi][nf], al[mi], bh[nj][sub], bh[nj][sub + 2]);
                }
        }
        __syncthreads();
    }

    #pragma unroll
    for (int mi = 0; mi < 2; mi++)
        #pragma unroll
        for (int nf = 0; nf < 4; nf++) {
            int row = m0 + wm + mi * 16 + (lane >> 2);
            int col = n0 + wn + nf * 8 + ((lane & 3) << 1);
            float2 v0; v0.x = acc[mi][nf][0]; v0.y = acc[mi][nf][1];
            float2 v1; v1.x = acc[mi][nf][2]; v1.y = acc[mi][nf][3];
            *(float2*)&C[(size_t)row * N + col]       = v0;
            *(float2*)&C[(size_t)(row + 8) * N + col] = v1;
        }
}

// ---------------- K3a: x_proj split-K partials with fused conv+SiLU ---------
// grid (NT/64, 4): block computes (48 x 64) over its 128-d slice.
__global__ void xproj_part_kernel(const float* __restrict__ W,
                                  const float* __restrict__ cw,
                                  const float* __restrict__ cb) {
    __shared__ float Ws[48][64];
    __shared__ float Xr[64][68];     // raw xz, col j <-> n0-4+j
    __shared__ float Xs[64][68];     // conv+silu, col c <-> n0+c
    __shared__ float Cw[64][4];
    __shared__ float Cb[64];
    int t  = threadIdx.x;
    int n0 = blockIdx.x * 64;
    int ks = blockIdx.y;
    int tn = t & 63, tk = t >> 6;
    bool seqstart = (n0 & (LSEQ - 1)) == 0;
    float acc[12];
    #pragma unroll
    for (int j = 0; j < 12; j++) acc[j] = 0.f;

    for (int cc = 0; cc < 2; cc++) {
        int d0 = ks * 128 + cc * 64;
        __syncthreads();
        for (int i = t; i < 768; i += 256) {
            int r = i >> 4, c4 = (i & 15) << 2;
            *(float4*)&Ws[r][c4] = *(const float4*)&W[(size_t)r * DIN + d0 + c4];
        }
        if (t < 64) {
            *(float4*)&Cw[t][0] = *(const float4*)&cw[(d0 + t) * 4];
            Cb[t] = cb[d0 + t];
        }
        for (int i = t; i < 1024; i += 256) {      // main cols j=4..67
            int r = i >> 4, c4 = (i & 15) << 2;
            *(float4*)&Xr[r][4 + c4] = *(const float4*)&g_xz[(size_t)(d0 + r) * NT + n0 + c4];
        }
        if (t < 192) {                              // history cols j=1..3
            int r = t / 3, j = t - r * 3;
            Xr[r][1 + j] = seqstart ? 0.f : g_xz[(size_t)(d0 + r) * NT + n0 - 3 + j];
        }
        __syncthreads();
        for (int i = t; i < 4096; i += 256) {
            int r = i >> 6, c = i & 63;
            float v = Cb[r];
            v = fmaf(Cw[r][3], Xr[r][c + 4], v);
            v = fmaf(Cw[r][2], Xr[r][c + 3], v);
            v = fmaf(Cw[r][1], Xr[r][c + 2], v);
            v = fmaf(Cw[r][0], Xr[r][c + 1], v);
            Xs[r][c] = v / (1.f + __expf(-v));
        }
        __syncthreads();
        #pragma unroll 4
        for (int dd = 0; dd < 64; dd++) {
            float xv = Xs[dd][tn];
            #pragma unroll
            for (int j = 0; j < 12; j++)
                acc[j] = fmaf(xv, Ws[tk * 12 + j][dd], acc[j]);
        }
    }
    int n = n0 + tn;
    #pragma unroll
    for (int j = 0; j < 12; j++) {
        int k = tk * 12 + j;
        g_xpart[((size_t)ks * 48 + k) * NT + n] = acc[j];
    }
}

// ---------------- K3b: reduce partials -> dt/Bm/Cm in (n,16) layout ---------
__global__ void xred_kernel() {
    int idx = blockIdx.x * 256 + threadIdx.x;       // 48 * NT
    int k = idx / NT, n = idx - k * NT;
    float s = g_xpart[(size_t)k * NT + n]
            + g_xpart[((size_t)48 + k) * NT + n]
            + g_xpart[((size_t)96 + k) * NT + n]
            + g_xpart[((size_t)144 + k) * NT + n];
    if (k < DTRANK)                g_dtarr[(size_t)n * 16 + k] = s;
    else if (k < DTRANK + DSTATE)  g_Bm[(size_t)n * 16 + (k - DTRANK)] = s;
    else                           g_Cm[(size_t)n * 16 + (k - DTRANK - DSTATE)] = s;
}

// ---------------- K4: delta = softplus(dt @ dtw^T + dtb) -> (DIN, NT) -------
__global__ void delta_kernel(const float* __restrict__ dtw,
                             const float* __restrict__ dtb) {
    int d = blockIdx.y;
    int n = blockIdx.x * 256 + threadIdx.x;
    float s = dtb[d];
    const float4* dtn = (const float4*)(g_dtarr + (size_t)n * 16);
    const float4* wr  = (const float4*)(dtw + d * 16);
    #pragma unroll
    for (int q = 0; q < 4; q++) {
        float4 a = dtn[q], b = wr[q];
        s += a.x * b.x + a.y * b.y + a.z * b.z + a.w * b.w;
    }
    float delta = (s > 20.f) ? s : log1pf(__expf(s));
    g_delta[(size_t)d * NT + n] = delta;
}

// ---------------- K5a: chunk scan pass1 (conv fused inline) -----------------
__global__ void scan_p1_kernel(const float* __restrict__ Alog,
                               const float* __restrict__ cw,
                               const float* __restrict__ cb) {
    int b  = blockIdx.z;
    int ch = blockIdx.y;
    int g  = threadIdx.x >> 4;
    int nl = threadIdx.x & 15;
    int d  = blockIdx.x * 16 + g;

    float Adn = -__expf(Alog[d * DSTATE + nl]);
    float w0 = cw[d * 4 + 0], w1 = cw[d * 4 + 1];
    float w2 = cw[d * 4 + 2], w3 = cw[d * 4 + 3];
    float bb = cb[d];
    float P = 1.f, q = 0.f;
    int base = b * LSEQ + ch * CHLEN;
    const float* xrow = g_xz + (size_t)d * NT + base;
    const float* drow = g_delta + (size_t)d * NT + base;
    const float* Bp   = g_Bm + (size_t)base * 16;

    float x1, x2, x3;
    if (ch == 0) { x1 = x2 = x3 = 0.f; }
    else { x1 = xrow[-1]; x2 = xrow[-2]; x3 = xrow[-3]; }

    #pragma unroll 4
    for (int l = 0; l < CHLEN; l++) {
        float x0 = xrow[l];
        float v = bb;
        v = fmaf(w3, x0, v); v = fmaf(w2, x1, v);
        v = fmaf(w1, x2, v); v = fmaf(w0, x3, v);
        float xc = v / (1.f + __expf(-v));
        x3 = x2; x2 = x1; x1 = x0;
        float delta = drow[l];
        float dA = __expf(delta * Adn);
        q = fmaf(dA, q, delta * Bp[l * 16 + nl] * xc);
        P *= dA;
    }
    size_t idx = ((size_t)(b * NCHUNK + ch) * DIN + d) * 16 + nl;
    g_P[idx] = P;
    g_q[idx] = q;
}

// ---------------- K5b: prefix over chunks -> h0 -----------------------------
__global__ void scan_p2_kernel() {
    int idx = blockIdx.x * 256 + threadIdx.x;
    int n = idx & 15;
    int d = (idx >> 4) & (DIN - 1);
    int b = idx >> 13;
    float h = 0.f;
    #pragma unroll
    for (int ch = 0; ch < NCHUNK; ch++) {
        size_t p = ((size_t)(b * NCHUNK + ch) * DIN + d) * 16 + n;
        g_h0[p] = h;
        h = fmaf(g_P[p], h, g_q[p]);
    }
}

// ---------------- K5c: replay + y + gating, emit y bf16 hi/lo (NT, DIN) -----
__global__ void scan_p3_kernel(const float* __restrict__ Alog,
                               const float* __restrict__ cw,
                               const float* __restrict__ cb,
                               const float* __restrict__ Dp) {
    int b  = blockIdx.z;
    int ch = blockIdx.y;
    int g  = threadIdx.x >> 4;
    int nl = threadIdx.x & 15;
    int d  = blockIdx.x * 16 + g;

    float Adn = -__expf(Alog[d * DSTATE + nl]);
    float w0 = cw[d * 4 + 0], w1 = cw[d * 4 + 1];
    float w2 = cw[d * 4 + 2], w3 = cw[d * 4 + 3];
    float bb = cb[d];
    float Dd  = Dp[d];
    float h = g_h0[((size_t)(b * NCHUNK + ch) * DIN + d) * 16 + nl];

    int base = b * LSEQ + ch * CHLEN;
    const float* xrow = g_xz + (size_t)d * NT + base;
    const float* drow = g_delta + (size_t)d * NT + base;
    const float* zrow = g_xz + (size_t)(DIN + d) * NT + base;
    const float* Bp = g_Bm + (size_t)base * 16;
    const float* Cp = g_Cm + (size_t)base * 16;

    float x1, x2, x3;
    if (ch == 0) { x1 = x2 = x3 = 0.f; }
    else { x1 = xrow[-1]; x2 = xrow[-2]; x3 = xrow[-3]; }

    #pragma unroll 4
    for (int l = 0; l < CHLEN; l++) {
        float x0 = xrow[l];
        float v = bb;
        v = fmaf(w3, x0, v); v = fmaf(w2, x1, v);
        v = fmaf(w1, x2, v); v = fmaf(w0, x3, v);
        float xc = v / (1.f + __expf(-v));
        x3 = x2; x2 = x1; x1 = x0;
        float delta = drow[l];
        float dA = __expf(delta * Adn);
        h = fmaf(dA, h, delta * Bp[l * 16 + nl] * xc);
        float yv = h * Cp[l * 16 + nl];
        yv += __shfl_xor_sync(0xffffffffu, yv, 1);
        yv += __shfl_xor_sync(0xffffffffu, yv, 2);
        yv += __shfl_xor_sync(0xffffffffu, yv, 4);
        yv += __shfl_xor_sync(0xffffffffu, yv, 8);
        if (nl == 0) {
            float zl = zrow[l];
            float silu = zl / (1.f + __expf(-zl));
            float outv = (yv + Dd * xc) * silu;
            __nv_bfloat16 hh = __float2bfloat16(outv);
            size_t yi = (size_t)(base + l) * DIN + d;
            g_y_h[yi] = hh;
            g_y_l[yi] = __float2bfloat16(outv - __bfloat162float(hh));
        }
    }
}

// ---------------- K6: residual + output LayerNorm, write (B,C,L,1) ----------
__global__ void ln_out_kernel(const float* __restrict__ x,
                              const float* __restrict__ w,
                              const float* __restrict__ bias,
                              float* __restrict__ out) {
    int b  = blockIdx.y;
    int lx = threadIdx.x;
    int ty = threadIdx.y;
    int l  = blockIdx.x * 32 + lx;
    __shared__ float sS[8][32], sQ[8][32], sMean[32], sR[32];

    const float* xb = x + (size_t)b * CDIM * LSEQ + l;
    const float* ob = g_op + (size_t)b * LSEQ + l;
    float s = 0.f, q = 0.f;
    for (int c = ty; c < CDIM; c += 8) {
        float v = ob[(size_t)c * NT] + xb[(size_t)c * LSEQ];
        s += v; q += v * v;
    }
    sS[ty][lx] = s; sQ[ty][lx] = q;
    __syncthreads();
    if (ty == 0) {
        float ts = 0.f, tq = 0.f;
        #pragma unroll
        for (int i = 0; i < 8; i++) { ts += sS[i][lx]; tq += sQ[i][lx]; }
        float m   = ts * (1.f / CDIM);
        float var = tq * (1.f / CDIM) - m * m;
        sMean[lx] = m;
        sR[lx]    = rsqrtf(var + 1e-5f);
    }
    __syncthreads();
    float m = sMean[lx], r = sR[lx];
    float* outb = out + (size_t)b * CDIM * LSEQ + l;
    for (int c = ty; c < CDIM; c += 8) {
        float v = ob[(size_t)c * NT] + xb[(size_t)c * LSEQ];
        outb[(size_t)c * LSEQ] = (v - m) * r * w[c] + bias[c];
    }
}

// ---------------- launch -----------------------------------------------------
extern "C" void kernel_launch(void* const* d_in, const int* in_sizes, int n_in,
                              void* d_out, int out_size) {
    const float* x         = (const float*)d_in[0];
    const float* ln_w      = (const float*)d_in[1];
    const float* ln_b      = (const float*)d_in[2];
    const float* in_proj_w = (const float*)d_in[3];
    const float* conv_w    = (const float*)d_in[4];
    const float* conv_b    = (const float*)d_in[5];
    const float* x_proj_w  = (const float*)d_in[6];
    const float* dt_proj_w = (const float*)d_in[7];
    const float* dt_proj_b = (const float*)d_in[8];
    const float* A_log     = (const float*)d_in[9];
    const float* Dv        = (const float*)d_in[10];
    const float* out_proj_w= (const float*)d_in[11];
    float* out = (float*)d_out;

    __nv_bfloat16 *p_uh, *p_ul, *p_wih, *p_wil, *p_woh, *p_wol, *p_yh, *p_yl;
    float *p_xz, *p_op;
    cudaGetSymbolAddress((void**)&p_uh,  g_u_h);
    cudaGetSymbolAddress((void**)&p_ul,  g_u_l);
    cudaGetSymbolAddress((void**)&p_wih, g_wih);
    cudaGetSymbolAddress((void**)&p_wil, g_wil);
    cudaGetSymbolAddress((void**)&p_woh, g_woh);
    cudaGetSymbolAddress((void**)&p_wol, g_wol);
    cudaGetSymbolAddress((void**)&p_yh,  g_y_h);
    cudaGetSymbolAddress((void**)&p_yl,  g_y_l);
    cudaGetSymbolAddress((void**)&p_xz,  g_xz);
    cudaGetSymbolAddress((void**)&p_op,  g_op);

    cvt_kernel<<<(2 * DIN * CDIM + CDIM * DIN) / 256, 256>>>(in_proj_w, out_proj_w);

    ln_in_kernel<<<dim3(LSEQ / 32, BATCH), 256>>>(x, ln_w, ln_b);

    // in_proj: (1024,256) @ (8192,256)^T -> grid (128, 8) = 1024 blocks
    gemm_bf16_kernel<<<dim3(NT / 64, (2 * DIN) / 128), 256>>>(
        p_wih, p_wil, p_uh, p_ul, p_xz, 2 * DIN, NT, CDIM);

    xproj_part_kernel<<<dim3(NT / 64, 4), 256>>>(x_proj_w, conv_w, conv_b);
    xred_kernel<<<(48 * NT) / 256, 256>>>();

    delta_kernel<<<dim3(NT / 256, DIN), 256>>>(dt_proj_w, dt_proj_b);

    scan_p1_kernel<<<dim3(DIN / 16, NCHUNK, BATCH), 256>>>(A_log, conv_w, conv_b);
    scan_p2_kernel<<<dim3(BATCH * DIN * 16 / 256), 256>>>();
    scan_p3_kernel<<<dim3(DIN / 16, NCHUNK, BATCH), 256>>>(A_log, conv_w, conv_b, Dv);

    // out_proj: (256,512) @ (8192,512)^T -> grid (128, 2) = 256 blocks
    gemm_bf16_kernel<<<dim3(NT / 64, CDIM / 128), 256>>>(
        p_woh, p_wol, p_yh, p_yl, p_op, CDIM, NT, DIN);

    ln_out_kernel<<<dim3(LSEQ / 32, BATCH), dim3(32, 8)>>>(x, ln_w, ln_b, out);
}

// round 6
// speedup vs baseline: 1.3841x; 1.3731x over previous
#include <cuda_runtime.h>
#include <cuda_bf16.h>
#include <math.h>
#include <stdint.h>

#define LSEQ   2048
#define BATCH  4
#define NT     8192          // BATCH * LSEQ
#define CDIM   256
#define DIN    512
#define DSTATE 16
#define DTRANK 16
#define NCHUNK 32
#define CHLEN  64            // LSEQ / NCHUNK

// ---------------- scratch (static __device__, no allocs) ----------------
__device__ float g_u    [NT * CDIM];        // (B*L, C)   n-major normalized input
__device__ float g_xz   [2 * DIN * NT];     // (2*DIN, B*L) in_proj output (m-major)
__device__ float g_xc   [DIN * NT];         // (DIN, B*L) conv+silu output
__device__ float g_xpart[4 * 48 * NT];      // x_proj split-K partials
__device__ float g_dt   [NT * DTRANK];      // (B*L, 16)
__device__ float g_Bm   [NT * DSTATE];      // (B*L, 16)
__device__ float g_Cm   [NT * DSTATE];      // (B*L, 16)
__device__ float g_delta[DIN * NT];         // (DIN, B*L) softplus(dt_proj)
__device__ float g_y    [NT * DIN];         // (B*L, DIN) n-major gated scan output
__device__ float g_op   [CDIM * NT];        // (C, B*L) out_proj output
__device__ float g_P    [BATCH * NCHUNK * DIN * DSTATE];
__device__ float g_q    [BATCH * NCHUNK * DIN * DSTATE];
__device__ float g_h0   [BATCH * NCHUNK * DIN * DSTATE];

__device__ __forceinline__ uint32_t s2u(const void* p) {
    return (uint32_t)__cvta_generic_to_shared(p);
}
__device__ __forceinline__ void ldsm4(uint32_t* r, uint32_t addr) {
    asm volatile("ldmatrix.sync.aligned.m8n8.x4.shared.b16 {%0,%1,%2,%3}, [%4];"
        : "=r"(r[0]), "=r"(r[1]), "=r"(r[2]), "=r"(r[3]) : "r"(addr));
}
__device__ __forceinline__ void mma16816(float* c, const uint32_t* a, uint32_t b0, uint32_t b1) {
    asm volatile("mma.sync.aligned.m16n8k16.row.col.f32.bf16.bf16.f32 "
        "{%0,%1,%2,%3}, {%4,%5,%6,%7}, {%8,%9}, {%0,%1,%2,%3};"
        : "+f"(c[0]), "+f"(c[1]), "+f"(c[2]), "+f"(c[3])
        : "r"(a[0]), "r"(a[1]), "r"(a[2]), "r"(a[3]), "r"(b0), "r"(b1));
}

// ---------------- K1: input LayerNorm (over C), output n-major (NT, C) ----
__global__ void ln_in_kernel(const float* __restrict__ x,
                             const float* __restrict__ w,
                             const float* __restrict__ bias) {
    int b  = blockIdx.y;
    int tid = threadIdx.x;
    int lx = tid & 31;
    int ty = tid >> 5;
    int l0 = blockIdx.x * 32;
    __shared__ float T[CDIM][33];
    __shared__ float sS[8][32], sQ[8][32], sMean[32], sR[32];

    const float* xb = x + (size_t)b * CDIM * LSEQ + l0 + lx;
    float s = 0.f, q = 0.f;
    for (int c = ty; c < CDIM; c += 8) {
        float v = xb[(size_t)c * LSEQ];
        T[c][lx] = v;
        s += v; q += v * v;
    }
    sS[ty][lx] = s; sQ[ty][lx] = q;
    __syncthreads();
    if (ty == 0) {
        float ts = 0.f, tq = 0.f;
        #pragma unroll
        for (int i = 0; i < 8; i++) { ts += sS[i][lx]; tq += sQ[i][lx]; }
        float m   = ts * (1.f / CDIM);
        float var = tq * (1.f / CDIM) - m * m;
        sMean[lx] = m;
        sR[lx]    = rsqrtf(var + 1e-5f);
    }
    __syncthreads();
    int c = tid;
    float wc = w[c], bc = bias[c];
    #pragma unroll 4
    for (int l = 0; l < 32; l++) {
        float v = T[c][l];
        g_u[(size_t)(b * LSEQ + l0 + l) * CDIM + c] = (v - sMean[l]) * sR[l] * wc + bc;
    }
}

// ---------------- K2: tensor-core TN GEMM with bf16 hi/lo split -------------
// C[M,N] = A[M,K] * Bn[N,K]^T.  A row-major (M,K), Bn row-major (N,K).
// BM=128 BN=64 BK=32; 8 warps as 4(m) x 2(n); warp tile 32x32.  (round-3 exact)
__global__ __launch_bounds__(256, 2)
void gemm_tc_kernel(const float* __restrict__ A, const float* __restrict__ Bn,
                    float* __restrict__ C, int M, int N, int K) {
    __shared__ __nv_bfloat16 Ah[128][40], Al[128][40], Bh[64][40], Bl[64][40];
    const int tid = threadIdx.x, lane = tid & 31, wid = tid >> 5;
    const int m0 = blockIdx.y * 128, n0 = blockIdx.x * 64;
    const int wm = (wid & 3) * 32;
    const int wn = (wid >> 2) * 32;
    const int lr = lane & 15;
    const int lc = (lane & 16) ? 8 : 0;

    float acc[2][4][4];
    #pragma unroll
    for (int mi = 0; mi < 2; mi++)
        #pragma unroll
        for (int nf = 0; nf < 4; nf++)
            #pragma unroll
            for (int e = 0; e < 4; e++) acc[mi][nf][e] = 0.f;

    const int grow = tid >> 3;           // 0..31
    const int gcol = (tid & 7) << 2;     // 0..28

    for (int k0 = 0; k0 < K; k0 += 32) {
        #pragma unroll
        for (int i = 0; i < 4; i++) {
            int r = grow + 32 * i;
            float4 v = *(const float4*)&A[(size_t)(m0 + r) * K + k0 + gcol];
            __nv_bfloat16 h0 = __float2bfloat16(v.x);
            __nv_bfloat16 h1 = __float2bfloat16(v.y);
            __nv_bfloat16 h2 = __float2bfloat16(v.z);
            __nv_bfloat16 h3 = __float2bfloat16(v.w);
            __nv_bfloat162 hh0; hh0.x = h0; hh0.y = h1;
            __nv_bfloat162 hh1; hh1.x = h2; hh1.y = h3;
            *(__nv_bfloat162*)&Ah[r][gcol]     = hh0;
            *(__nv_bfloat162*)&Ah[r][gcol + 2] = hh1;
            __nv_bfloat162 ll0, ll1;
            ll0.x = __float2bfloat16(v.x - __bfloat162float(h0));
            ll0.y = __float2bfloat16(v.y - __bfloat162float(h1));
            ll1.x = __float2bfloat16(v.z - __bfloat162float(h2));
            ll1.y = __float2bfloat16(v.w - __bfloat162float(h3));
            *(__nv_bfloat162*)&Al[r][gcol]     = ll0;
            *(__nv_bfloat162*)&Al[r][gcol + 2] = ll1;
        }
        #pragma unroll
        for (int i = 0; i < 2; i++) {
            int r = grow + 32 * i;
            float4 v = *(const float4*)&Bn[(size_t)(n0 + r) * K + k0 + gcol];
            __nv_bfloat16 h0 = __float2bfloat16(v.x);
            __nv_bfloat16 h1 = __float2bfloat16(v.y);
            __nv_bfloat16 h2 = __float2bfloat16(v.z);
            __nv_bfloat16 h3 = __float2bfloat16(v.w);
            __nv_bfloat162 hh0; hh0.x = h0; hh0.y = h1;
            __nv_bfloat162 hh1; hh1.x = h2; hh1.y = h3;
            *(__nv_bfloat162*)&Bh[r][gcol]     = hh0;
            *(__nv_bfloat162*)&Bh[r][gcol + 2] = hh1;
            __nv_bfloat162 ll0, ll1;
            ll0.x = __float2bfloat16(v.x - __bfloat162float(h0));
            ll0.y = __float2bfloat16(v.y - __bfloat162float(h1));
            ll1.x = __float2bfloat16(v.z - __bfloat162float(h2));
            ll1.y = __float2bfloat16(v.w - __bfloat162float(h3));
            *(__nv_bfloat162*)&Bl[r][gcol]     = ll0;
            *(__nv_bfloat162*)&Bl[r][gcol + 2] = ll1;
        }
        __syncthreads();

        #pragma unroll
        for (int kk = 0; kk < 2; kk++) {
            const int k16 = kk * 16;
            uint32_t ah[2][4], al[2][4], bh[2][4], bl[2][4];
            #pragma unroll
            for (int mi = 0; mi < 2; mi++) {
                ldsm4(ah[mi], s2u(&Ah[wm + mi * 16 + lr][k16 + lc]));
                ldsm4(al[mi], s2u(&Al[wm + mi * 16 + lr][k16 + lc]));
            }
            #pragma unroll
            for (int nj = 0; nj < 2; nj++) {
                ldsm4(bh[nj], s2u(&Bh[wn + nj * 16 + lr][k16 + lc]));
                ldsm4(bl[nj], s2u(&Bl[wn + nj * 16 + lr][k16 + lc]));
            }
            #pragma unroll
            for (int mi = 0; mi < 2; mi++)
                #pragma unroll
                for (int nf = 0; nf < 4; nf++) {
                    int nj = nf >> 1, sub = nf & 1;
                    mma16816(acc[mi][nf], ah[mi], bh[nj][sub], bh[nj][sub + 2]);
                    mma16816(acc[mi][nf], ah[mi], bl[nj][sub], bl[nj][sub + 2]);
                    mma16816(acc[mi][nf], al[mi], bh[nj][sub], bh[nj][sub + 2]);
                }
        }
        __syncthreads();
    }

    #pragma unroll
    for (int mi = 0; mi < 2; mi++)
        #pragma unroll
        for (int nf = 0; nf < 4; nf++) {
            int row = m0 + wm + mi * 16 + (lane >> 2);
            int col = n0 + wn + nf * 8 + ((lane & 3) << 1);
            float2 v0; v0.x = acc[mi][nf][0]; v0.y = acc[mi][nf][1];
            float2 v1; v1.x = acc[mi][nf][2]; v1.y = acc[mi][nf][3];
            *(float2*)&C[(size_t)row * N + col]       = v0;
            *(float2*)&C[(size_t)(row + 8) * N + col] = v1;
        }
}

// ---------------- K3: causal depthwise conv (width 4) + SiLU ----------------
__global__ void conv_kernel(const float* __restrict__ cw,
                            const float* __restrict__ cb) {
    int d = blockIdx.y;
    int n = blockIdx.x * 256 + threadIdx.x;
    const float* xin = g_xz + (size_t)d * NT;
    float w0 = cw[d * 4 + 0], w1 = cw[d * 4 + 1];
    float w2 = cw[d * 4 + 2], w3 = cw[d * 4 + 3];
    int l = n & (LSEQ - 1);
    float v = cb[d] + w3 * xin[n];
    if (l >= 1) v = fmaf(w2, xin[n - 1], v);
    if (l >= 2) v = fmaf(w1, xin[n - 2], v);
    if (l >= 3) v = fmaf(w0, xin[n - 3], v);
    v = v / (1.f + __expf(-v));          // SiLU
    g_xc[(size_t)d * NT + n] = v;
}

// ---------------- K4a: x_proj split-K partials ------------------------------
__global__ void xproj_part_kernel(const float* __restrict__ W) {
    __shared__ float Ws[48][64];
    __shared__ float Xs[64][68];
    int t  = threadIdx.x;
    int n0 = blockIdx.x * 64;
    int ks = blockIdx.y;
    int tn = t & 63, tk = t >> 6;
    float acc[12];
    #pragma unroll
    for (int j = 0; j < 12; j++) acc[j] = 0.f;

    for (int cc = 0; cc < 2; cc++) {
        int d0 = ks * 128 + cc * 64;
        __syncthreads();
        for (int i = t; i < 768; i += 256) {
            int r = i >> 4, c4 = (i & 15) << 2;
            *(float4*)&Ws[r][c4] = *(const float4*)&W[(size_t)r * DIN + d0 + c4];
        }
        for (int i = t; i < 1024; i += 256) {
            int r = i >> 4, c4 = (i & 15) << 2;
            *(float4*)&Xs[r][c4] = *(const float4*)&g_xc[(size_t)(d0 + r) * NT + n0 + c4];
        }
        __syncthreads();
        #pragma unroll 4
        for (int dd = 0; dd < 64; dd++) {
            float xv = Xs[dd][tn];
            #pragma unroll
            for (int j = 0; j < 12; j++)
                acc[j] = fmaf(xv, Ws[tk * 12 + j][dd], acc[j]);
        }
    }
    int n = n0 + tn;
    #pragma unroll
    for (int j = 0; j < 12; j++) {
        int k = tk * 12 + j;
        g_xpart[((size_t)ks * 48 + k) * NT + n] = acc[j];
    }
}

// ---------------- K4b: reduce partials -> dt/Bm/Cm in (n,16) layout ---------
__global__ void xred_kernel() {
    int idx = blockIdx.x * 256 + threadIdx.x;       // 48 * NT
    int k = idx / NT, n = idx - k * NT;
    float s = g_xpart[(size_t)k * NT + n]
            + g_xpart[((size_t)48 + k) * NT + n]
            + g_xpart[((size_t)96 + k) * NT + n]
            + g_xpart[((size_t)144 + k) * NT + n];
    if (k < DTRANK)                g_dt[(size_t)n * 16 + k] = s;
    else if (k < DTRANK + DSTATE)  g_Bm[(size_t)n * 16 + (k - DTRANK)] = s;
    else                           g_Cm[(size_t)n * 16 + (k - DTRANK - DSTATE)] = s;
}

// ---------------- K5: delta = softplus(dt @ dtw^T + dtb), smem-tiled --------
// grid (NT/256, 4): block covers 256 n's x 128 d's.
__global__ void delta_kernel(const float* __restrict__ dtw,
                             const float* __restrict__ dtb) {
    __shared__ float sDt[256][17];
    __shared__ float sW[128][17];
    __shared__ float sB[128];
    int t = threadIdx.x;
    int n0 = blockIdx.x * 256;
    int dseg = blockIdx.y * 128;

    for (int i = t; i < 256 * 4; i += 256) {
        int r = i >> 2, c4 = (i & 3) << 2;
        float4 v = *(const float4*)&g_dt[(size_t)(n0 + r) * 16 + c4];
        sDt[r][c4 + 0] = v.x; sDt[r][c4 + 1] = v.y;
        sDt[r][c4 + 2] = v.z; sDt[r][c4 + 3] = v.w;
    }
    for (int i = t; i < 128 * 4; i += 256) {
        int r = i >> 2, c4 = (i & 3) << 2;
        float4 v = *(const float4*)&dtw[(size_t)(dseg + r) * 16 + c4];
        sW[r][c4 + 0] = v.x; sW[r][c4 + 1] = v.y;
        sW[r][c4 + 2] = v.z; sW[r][c4 + 3] = v.w;
    }
    if (t < 128) sB[t] = dtb[dseg + t];
    __syncthreads();

    int n = n0 + t;
    for (int dd = 0; dd < 128; dd++) {
        float s = sB[dd];
        #pragma unroll
        for (int k = 0; k < 16; k++)
            s = fmaf(sDt[t][k], sW[dd][k], s);
        float delta = (s > 20.f) ? s : log1pf(__expf(s));
        g_delta[(size_t)(dseg + dd) * NT + n] = delta;
    }
}

// ---------------- K6a: chunk scan pass1 — smem-shared B chunk ---------------
// grid (4 dtile, NCHUNK, BATCH); block 256 = 16 groups x 16 lanes; 8 d per group.
__global__ void scan_p1_kernel(const float* __restrict__ Alog) {
    __shared__ float sB[CHLEN][16];
    int b  = blockIdx.z;
    int ch = blockIdx.y;
    int g  = threadIdx.x >> 4;
    int nl = threadIdx.x & 15;
    int d0 = blockIdx.x * 128;
    int base = b * LSEQ + ch * CHLEN;

    {
        int t = threadIdx.x;
        float4 v = *(const float4*)&g_Bm[((size_t)base) * 16 + t * 4];
        *(float4*)&sB[(t * 4) >> 4][(t * 4) & 15] = v;
    }
    __syncthreads();

    for (int dt = 0; dt < 8; dt++) {
        int d = d0 + dt * 16 + g;
        float Adn = -__expf(Alog[d * DSTATE + nl]);
        float P = 1.f, q = 0.f;
        const float* drow  = g_delta + (size_t)d * NT + base;
        const float* xcrow = g_xc    + (size_t)d * NT + base;
        #pragma unroll 4
        for (int l = 0; l < CHLEN; l++) {
            float delta = drow[l];
            float dA = __expf(delta * Adn);
            q = fmaf(dA, q, delta * sB[l][nl] * xcrow[l]);
            P *= dA;
        }
        size_t idx = ((size_t)(b * NCHUNK + ch) * DIN + d) * 16 + nl;
        g_P[idx] = P;
        g_q[idx] = q;
    }
}

// ---------------- K6b: prefix over chunks -> h0 -----------------------------
__global__ void scan_p2_kernel() {
    int idx = blockIdx.x * 256 + threadIdx.x;
    int n = idx & 15;
    int d = (idx >> 4) & (DIN - 1);
    int b = idx >> 13;
    float h = 0.f;
    #pragma unroll
    for (int ch = 0; ch < NCHUNK; ch++) {
        size_t p = ((size_t)(b * NCHUNK + ch) * DIN + d) * 16 + n;
        g_h0[p] = h;
        h = fmaf(g_P[p], h, g_q[p]);
    }
}

// ---------------- K6c: replay + y + gating — smem-shared B/C chunks ---------
__global__ void scan_p3_kernel(const float* __restrict__ Alog,
                               const float* __restrict__ Dp) {
    __shared__ float sB[CHLEN][16];
    __shared__ float sC[CHLEN][16];
    int b  = blockIdx.z;
    int ch = blockIdx.y;
    int g  = threadIdx.x >> 4;
    int nl = threadIdx.x & 15;
    int d0 = blockIdx.x * 128;
    int base = b * LSEQ + ch * CHLEN;

    {
        int t = threadIdx.x;
        float4 v = *(const float4*)&g_Bm[((size_t)base) * 16 + t * 4];
        *(float4*)&sB[(t * 4) >> 4][(t * 4) & 15] = v;
        float4 w = *(const float4*)&g_Cm[((size_t)base) * 16 + t * 4];
        *(float4*)&sC[(t * 4) >> 4][(t * 4) & 15] = w;
    }
    __syncthreads();

    for (int dt = 0; dt < 8; dt++) {
        int d = d0 + dt * 16 + g;
        float Adn = -__expf(Alog[d * DSTATE + nl]);
        float Dd  = Dp[d];
        float h = g_h0[((size_t)(b * NCHUNK + ch) * DIN + d) * 16 + nl];
        const float* drow  = g_delta + (size_t)d * NT + base;
        const float* xcrow = g_xc    + (size_t)d * NT + base;
        const float* zrow  = g_xz + (size_t)(DIN + d) * NT + base;
        #pragma unroll 4
        for (int l = 0; l < CHLEN; l++) {
            float delta = drow[l];
            float xcv = xcrow[l];
            float dA = __expf(delta * Adn);
            h = fmaf(dA, h, delta * sB[l][nl] * xcv);
            float yv = h * sC[l][nl];
            yv += __shfl_xor_sync(0xffffffffu, yv, 1);
            yv += __shfl_xor_sync(0xffffffffu, yv, 2);
            yv += __shfl_xor_sync(0xffffffffu, yv, 4);
            yv += __shfl_xor_sync(0xffffffffu, yv, 8);
            if (nl == 0) {
                float zl = zrow[l];
                float silu = zl / (1.f + __expf(-zl));
                g_y[(size_t)(base + l) * DIN + d] = (yv + Dd * xcv) * silu;
            }
        }
    }
}

// ---------------- K7: residual + output LayerNorm, write (B,C,L,1) ----------
__global__ void ln_out_kernel(const float* __restrict__ x,
                              const float* __restrict__ w,
                              const float* __restrict__ bias,
                              float* __restrict__ out) {
    int b  = blockIdx.y;
    int lx = threadIdx.x;
    int ty = threadIdx.y;
    int l  = blockIdx.x * 32 + lx;
    __shared__ float sS[8][32], sQ[8][32], sMean[32], sR[32];

    const float* xb = x + (size_t)b * CDIM * LSEQ + l;
    const float* ob = g_op + (size_t)b * LSEQ + l;
    float s = 0.f, q = 0.f;
    for (int c = ty; c < CDIM; c += 8) {
        float v = ob[(size_t)c * NT] + xb[(size_t)c * LSEQ];
        s += v; q += v * v;
    }
    sS[ty][lx] = s; sQ[ty][lx] = q;
    __syncthreads();
    if (ty == 0) {
        float ts = 0.f, tq = 0.f;
        #pragma unroll
        for (int i = 0; i < 8; i++) { ts += sS[i][lx]; tq += sQ[i][lx]; }
        float m   = ts * (1.f / CDIM);
        float var = tq * (1.f / CDIM) - m * m;
        sMean[lx] = m;
        sR[lx]    = rsqrtf(var + 1e-5f);
    }
    __syncthreads();
    float m = sMean[lx], r = sR[lx];
    float* outb = out + (size_t)b * CDIM * LSEQ + l;
    for (int c = ty; c < CDIM; c += 8) {
        float v = ob[(size_t)c * NT] + xb[(size_t)c * LSEQ];
        outb[(size_t)c * LSEQ] = (v - m) * r * w[c] + bias[c];
    }
}

// ---------------- launch -----------------------------------------------------
extern "C" void kernel_launch(void* const* d_in, const int* in_sizes, int n_in,
                              void* d_out, int out_size) {
    const float* x         = (const float*)d_in[0];
    const float* ln_w      = (const float*)d_in[1];
    const float* ln_b      = (const float*)d_in[2];
    const float* in_proj_w = (const float*)d_in[3];
    const float* conv_w    = (const float*)d_in[4];
    const float* conv_b    = (const float*)d_in[5];
    const float* x_proj_w  = (const float*)d_in[6];
    const float* dt_proj_w = (const float*)d_in[7];
    const float* dt_proj_b = (const float*)d_in[8];
    const float* A_log     = (const float*)d_in[9];
    const float* Dv        = (const float*)d_in[10];
    const float* out_proj_w= (const float*)d_in[11];
    float* out = (float*)d_out;

    float *p_u, *p_xz, *p_y, *p_op;
    cudaGetSymbolAddress((void**)&p_u,  g_u);
    cudaGetSymbolAddress((void**)&p_xz, g_xz);
    cudaGetSymbolAddress((void**)&p_y,  g_y);
    cudaGetSymbolAddress((void**)&p_op, g_op);

    ln_in_kernel<<<dim3(LSEQ / 32, BATCH), 256>>>(x, ln_w, ln_b);

    // in_proj: (1024,256) @ (8192,256)^T
    gemm_tc_kernel<<<dim3(NT / 64, (2 * DIN) / 128), 256>>>(
        in_proj_w, p_u, p_xz, 2 * DIN, NT, CDIM);

    conv_kernel<<<dim3(NT / 256, DIN), 256>>>(conv_w, conv_b);

    xproj_part_kernel<<<dim3(NT / 64, 4), 256>>>(x_proj_w);
    xred_kernel<<<(48 * NT) / 256, 256>>>();

    delta_kernel<<<dim3(NT / 256, 4), 256>>>(dt_proj_w, dt_proj_b);

    scan_p1_kernel<<<dim3(4, NCHUNK, BATCH), 256>>>(A_log);
    scan_p2_kernel<<<dim3(BATCH * DIN * 16 / 256), 256>>>();
    scan_p3_kernel<<<dim3(4, NCHUNK, BATCH), 256>>>(A_log, Dv);

    // out_proj: (256,512) @ (8192,512)^T
    gemm_tc_kernel<<<dim3(NT / 64, CDIM / 128), 256>>>(
        out_proj_w, p_y, p_op, CDIM, NT, DIN);

    ln_out_kernel<<<dim3(LSEQ / 32, BATCH), dim3(32, 8)>>>(x, ln_w, ln_b, out);
}

// round 7
// speedup vs baseline: 1.3894x; 1.0039x over previous
#include <cuda_runtime.h>
#include <cuda_bf16.h>
#include <math.h>
#include <stdint.h>

#define LSEQ   2048
#define BATCH  4
#define NT     8192          // BATCH * LSEQ
#define CDIM   256
#define DIN    512
#define DSTATE 16
#define DTRANK 16
#define NCHUNK 32
#define CHLEN  64            // LSEQ / NCHUNK

// ---------------- scratch (static __device__, no allocs) ----------------
__device__ float g_u    [NT * CDIM];        // (B*L, C)   n-major normalized input
__device__ float g_xz   [2 * DIN * NT];     // (2*DIN, B*L) in_proj output (m-major)
__device__ float g_xc   [DIN * NT];         // (DIN, B*L) conv+silu output
__device__ float g_xpart[4 * 48 * NT];      // x_proj split-K partials
__device__ float g_dt   [NT * DTRANK];      // (B*L, 16)
__device__ float g_Bm   [NT * DSTATE];      // (B*L, 16)
__device__ float g_Cm   [NT * DSTATE];      // (B*L, 16)
__device__ float g_delta[DIN * NT];         // (DIN, B*L) softplus(dt_proj)
__device__ float g_y    [NT * DIN];         // (B*L, DIN) n-major gated scan output
__device__ float g_op   [CDIM * NT];        // (C, B*L) out_proj output
__device__ float g_P    [BATCH * NCHUNK * DIN * DSTATE];
__device__ float g_q    [BATCH * NCHUNK * DIN * DSTATE];
__device__ float g_h0   [BATCH * NCHUNK * DIN * DSTATE];

__device__ __forceinline__ uint32_t s2u(const void* p) {
    return (uint32_t)__cvta_generic_to_shared(p);
}
__device__ __forceinline__ void ldsm4(uint32_t* r, uint32_t addr) {
    asm volatile("ldmatrix.sync.aligned.m8n8.x4.shared.b16 {%0,%1,%2,%3}, [%4];"
        : "=r"(r[0]), "=r"(r[1]), "=r"(r[2]), "=r"(r[3]) : "r"(addr));
}
__device__ __forceinline__ void mma16816(float* c, const uint32_t* a, uint32_t b0, uint32_t b1) {
    asm volatile("mma.sync.aligned.m16n8k16.row.col.f32.bf16.bf16.f32 "
        "{%0,%1,%2,%3}, {%4,%5,%6,%7}, {%8,%9}, {%0,%1,%2,%3};"
        : "+f"(c[0]), "+f"(c[1]), "+f"(c[2]), "+f"(c[3])
        : "r"(a[0]), "r"(a[1]), "r"(a[2]), "r"(a[3]), "r"(b0), "r"(b1));
}

// ---------------- K1: input LayerNorm (over C), output n-major (NT, C) ----
__global__ void ln_in_kernel(const float* __restrict__ x,
                             const float* __restrict__ w,
                             const float* __restrict__ bias) {
    int b  = blockIdx.y;
    int tid = threadIdx.x;
    int lx = tid & 31;
    int ty = tid >> 5;
    int l0 = blockIdx.x * 32;
    __shared__ float T[CDIM][33];
    __shared__ float sS[8][32], sQ[8][32], sMean[32], sR[32];

    const float* xb = x + (size_t)b * CDIM * LSEQ + l0 + lx;
    float s = 0.f, q = 0.f;
    for (int c = ty; c < CDIM; c += 8) {
        float v = xb[(size_t)c * LSEQ];
        T[c][lx] = v;
        s += v; q += v * v;
    }
    sS[ty][lx] = s; sQ[ty][lx] = q;
    __syncthreads();
    if (ty == 0) {
        float ts = 0.f, tq = 0.f;
        #pragma unroll
        for (int i = 0; i < 8; i++) { ts += sS[i][lx]; tq += sQ[i][lx]; }
        float m   = ts * (1.f / CDIM);
        float var = tq * (1.f / CDIM) - m * m;
        sMean[lx] = m;
        sR[lx]    = rsqrtf(var + 1e-5f);
    }
    __syncthreads();
    int c = tid;
    float wc = w[c], bc = bias[c];
    #pragma unroll 4
    for (int l = 0; l < 32; l++) {
        float v = T[c][l];
        g_u[(size_t)(b * LSEQ + l0 + l) * CDIM + c] = (v - sMean[l]) * sR[l] * wc + bc;
    }
}

// ---------------- K2: tensor-core TN GEMM, bf16 hi/lo, reg-prefetch ---------
// C[M,N] = A[M,K] * Bn[N,K]^T.  BM=128 BN=64 BK=32; 8 warps 4(m)x2(n).
__global__ __launch_bounds__(256, 2)
void gemm_tc_kernel(const float* __restrict__ A, const float* __restrict__ Bn,
                    float* __restrict__ C, int M, int N, int K) {
    __shared__ __nv_bfloat16 Ah[128][40], Al[128][40], Bh[64][40], Bl[64][40];
    const int tid = threadIdx.x, lane = tid & 31, wid = tid >> 5;
    const int m0 = blockIdx.y * 128, n0 = blockIdx.x * 64;
    const int wm = (wid & 3) * 32;
    const int wn = (wid >> 2) * 32;
    const int lr = lane & 15;
    const int lc = (lane & 16) ? 8 : 0;

    float acc[2][4][4];
    #pragma unroll
    for (int mi = 0; mi < 2; mi++)
        #pragma unroll
        for (int nf = 0; nf < 4; nf++)
            #pragma unroll
            for (int e = 0; e < 4; e++) acc[mi][nf][e] = 0.f;

    const int grow = tid >> 3;           // 0..31
    const int gcol = (tid & 7) << 2;     // 0..28

    const float* Abase = A + (size_t)(m0 + grow) * K + gcol;
    const float* Bbase = Bn + (size_t)(n0 + grow) * K + gcol;

    float4 va[4], vb[2];
    #pragma unroll
    for (int i = 0; i < 4; i++) va[i] = *(const float4*)(Abase + (size_t)(32 * i) * K);
    #pragma unroll
    for (int i = 0; i < 2; i++) vb[i] = *(const float4*)(Bbase + (size_t)(32 * i) * K);

    const int nk = K >> 5;
    for (int kt = 0; kt < nk; kt++) {
        // ---- store+convert current regs to smem ----
        #pragma unroll
        for (int i = 0; i < 4; i++) {
            int r = grow + 32 * i;
            float4 v = va[i];
            __nv_bfloat16 h0 = __float2bfloat16(v.x);
            __nv_bfloat16 h1 = __float2bfloat16(v.y);
            __nv_bfloat16 h2 = __float2bfloat16(v.z);
            __nv_bfloat16 h3 = __float2bfloat16(v.w);
            __nv_bfloat162 hh0; hh0.x = h0; hh0.y = h1;
            __nv_bfloat162 hh1; hh1.x = h2; hh1.y = h3;
            *(__nv_bfloat162*)&Ah[r][gcol]     = hh0;
            *(__nv_bfloat162*)&Ah[r][gcol + 2] = hh1;
            __nv_bfloat162 ll0, ll1;
            ll0.x = __float2bfloat16(v.x - __bfloat162float(h0));
            ll0.y = __float2bfloat16(v.y - __bfloat162float(h1));
            ll1.x = __float2bfloat16(v.z - __bfloat162float(h2));
            ll1.y = __float2bfloat16(v.w - __bfloat162float(h3));
            *(__nv_bfloat162*)&Al[r][gcol]     = ll0;
            *(__nv_bfloat162*)&Al[r][gcol + 2] = ll1;
        }
        #pragma unroll
        for (int i = 0; i < 2; i++) {
            int r = grow + 32 * i;
            float4 v = vb[i];
            __nv_bfloat16 h0 = __float2bfloat16(v.x);
            __nv_bfloat16 h1 = __float2bfloat16(v.y);
            __nv_bfloat16 h2 = __float2bfloat16(v.z);
            __nv_bfloat16 h3 = __float2bfloat16(v.w);
            __nv_bfloat162 hh0; hh0.x = h0; hh0.y = h1;
            __nv_bfloat162 hh1; hh1.x = h2; hh1.y = h3;
            *(__nv_bfloat162*)&Bh[r][gcol]     = hh0;
            *(__nv_bfloat162*)&Bh[r][gcol + 2] = hh1;
            __nv_bfloat162 ll0, ll1;
            ll0.x = __float2bfloat16(v.x - __bfloat162float(h0));
            ll0.y = __float2bfloat16(v.y - __bfloat162float(h1));
            ll1.x = __float2bfloat16(v.z - __bfloat162float(h2));
            ll1.y = __float2bfloat16(v.w - __bfloat162float(h3));
            *(__nv_bfloat162*)&Bl[r][gcol]     = ll0;
            *(__nv_bfloat162*)&Bl[r][gcol + 2] = ll1;
        }
        __syncthreads();

        // ---- prefetch next k-tile into regs (overlaps MMA section) ----
        if (kt + 1 < nk) {
            const float* Ap = Abase + (kt + 1) * 32;
            const float* Bp = Bbase + (kt + 1) * 32;
            #pragma unroll
            for (int i = 0; i < 4; i++) va[i] = *(const float4*)(Ap + (size_t)(32 * i) * K);
            #pragma unroll
            for (int i = 0; i < 2; i++) vb[i] = *(const float4*)(Bp + (size_t)(32 * i) * K);
        }

        #pragma unroll
        for (int kk = 0; kk < 2; kk++) {
            const int k16 = kk * 16;
            uint32_t ah[2][4], al[2][4], bh[2][4], bl[2][4];
            #pragma unroll
            for (int mi = 0; mi < 2; mi++) {
                ldsm4(ah[mi], s2u(&Ah[wm + mi * 16 + lr][k16 + lc]));
                ldsm4(al[mi], s2u(&Al[wm + mi * 16 + lr][k16 + lc]));
            }
            #pragma unroll
            for (int nj = 0; nj < 2; nj++) {
                ldsm4(bh[nj], s2u(&Bh[wn + nj * 16 + lr][k16 + lc]));
                ldsm4(bl[nj], s2u(&Bl[wn + nj * 16 + lr][k16 + lc]));
            }
            #pragma unroll
            for (int mi = 0; mi < 2; mi++)
                #pragma unroll
                for (int nf = 0; nf < 4; nf++) {
                    int nj = nf >> 1, sub = nf & 1;
                    mma16816(acc[mi][nf], ah[mi], bh[nj][sub], bh[nj][sub + 2]);
                    mma16816(acc[mi][nf], ah[mi], bl[nj][sub], bl[nj][sub + 2]);
                    mma16816(acc[mi][nf], al[mi], bh[nj][sub], bh[nj][sub + 2]);
                }
        }
        __syncthreads();
    }

    #pragma unroll
    for (int mi = 0; mi < 2; mi++)
        #pragma unroll
        for (int nf = 0; nf < 4; nf++) {
            int row = m0 + wm + mi * 16 + (lane >> 2);
            int col = n0 + wn + nf * 8 + ((lane & 3) << 1);
            float2 v0; v0.x = acc[mi][nf][0]; v0.y = acc[mi][nf][1];
            float2 v1; v1.x = acc[mi][nf][2]; v1.y = acc[mi][nf][3];
            *(float2*)&C[(size_t)row * N + col]       = v0;
            *(float2*)&C[(size_t)(row + 8) * N + col] = v1;
        }
}

// ---------------- K3: causal depthwise conv (width 4) + SiLU ----------------
__global__ void conv_kernel(const float* __restrict__ cw,
                            const float* __restrict__ cb) {
    int d = blockIdx.y;
    int n = blockIdx.x * 256 + threadIdx.x;
    const float* xin = g_xz + (size_t)d * NT;
    float w0 = cw[d * 4 + 0], w1 = cw[d * 4 + 1];
    float w2 = cw[d * 4 + 2], w3 = cw[d * 4 + 3];
    int l = n & (LSEQ - 1);
    float v = cb[d] + w3 * xin[n];
    if (l >= 1) v = fmaf(w2, xin[n - 1], v);
    if (l >= 2) v = fmaf(w1, xin[n - 2], v);
    if (l >= 3) v = fmaf(w0, xin[n - 3], v);
    v = v / (1.f + __expf(-v));          // SiLU
    g_xc[(size_t)d * NT + n] = v;
}

// ---------------- K4a: x_proj split-K partials ------------------------------
__global__ void xproj_part_kernel(const float* __restrict__ W) {
    __shared__ float Ws[48][64];
    __shared__ float Xs[64][68];
    int t  = threadIdx.x;
    int n0 = blockIdx.x * 64;
    int ks = blockIdx.y;
    int tn = t & 63, tk = t >> 6;
    float acc[12];
    #pragma unroll
    for (int j = 0; j < 12; j++) acc[j] = 0.f;

    for (int cc = 0; cc < 2; cc++) {
        int d0 = ks * 128 + cc * 64;
        __syncthreads();
        for (int i = t; i < 768; i += 256) {
            int r = i >> 4, c4 = (i & 15) << 2;
            *(float4*)&Ws[r][c4] = *(const float4*)&W[(size_t)r * DIN + d0 + c4];
        }
        for (int i = t; i < 1024; i += 256) {
            int r = i >> 4, c4 = (i & 15) << 2;
            *(float4*)&Xs[r][c4] = *(const float4*)&g_xc[(size_t)(d0 + r) * NT + n0 + c4];
        }
        __syncthreads();
        #pragma unroll 4
        for (int dd = 0; dd < 64; dd++) {
            float xv = Xs[dd][tn];
            #pragma unroll
            for (int j = 0; j < 12; j++)
                acc[j] = fmaf(xv, Ws[tk * 12 + j][dd], acc[j]);
        }
    }
    int n = n0 + tn;
    #pragma unroll
    for (int j = 0; j < 12; j++) {
        int k = tk * 12 + j;
        g_xpart[((size_t)ks * 48 + k) * NT + n] = acc[j];
    }
}

// ---------------- K4b: reduce partials -> dt/Bm/Cm in (n,16) layout ---------
__global__ void xred_kernel() {
    int idx = blockIdx.x * 256 + threadIdx.x;       // 48 * NT
    int k = idx / NT, n = idx - k * NT;
    float s = g_xpart[(size_t)k * NT + n]
            + g_xpart[((size_t)48 + k) * NT + n]
            + g_xpart[((size_t)96 + k) * NT + n]
            + g_xpart[((size_t)144 + k) * NT + n];
    if (k < DTRANK)                g_dt[(size_t)n * 16 + k] = s;
    else if (k < DTRANK + DSTATE)  g_Bm[(size_t)n * 16 + (k - DTRANK)] = s;
    else                           g_Cm[(size_t)n * 16 + (k - DTRANK - DSTATE)] = s;
}

// ---------------- K5: delta = softplus(dt @ dtw^T + dtb), smem-tiled --------
__global__ void delta_kernel(const float* __restrict__ dtw,
                             const float* __restrict__ dtb) {
    __shared__ float sDt[256][17];
    __shared__ float sW[128][17];
    __shared__ float sB[128];
    int t = threadIdx.x;
    int n0 = blockIdx.x * 256;
    int dseg = blockIdx.y * 128;

    for (int i = t; i < 256 * 4; i += 256) {
        int r = i >> 2, c4 = (i & 3) << 2;
        float4 v = *(const float4*)&g_dt[(size_t)(n0 + r) * 16 + c4];
        sDt[r][c4 + 0] = v.x; sDt[r][c4 + 1] = v.y;
        sDt[r][c4 + 2] = v.z; sDt[r][c4 + 3] = v.w;
    }
    for (int i = t; i < 128 * 4; i += 256) {
        int r = i >> 2, c4 = (i & 3) << 2;
        float4 v = *(const float4*)&dtw[(size_t)(dseg + r) * 16 + c4];
        sW[r][c4 + 0] = v.x; sW[r][c4 + 1] = v.y;
        sW[r][c4 + 2] = v.z; sW[r][c4 + 3] = v.w;
    }
    if (t < 128) sB[t] = dtb[dseg + t];
    __syncthreads();

    int n = n0 + t;
    for (int dd = 0; dd < 128; dd++) {
        float s = sB[dd];
        #pragma unroll
        for (int k = 0; k < 16; k++)
            s = fmaf(sDt[t][k], sW[dd][k], s);
        float delta = (s > 20.f) ? s : log1pf(__expf(s));
        g_delta[(size_t)(dseg + dd) * NT + n] = delta;
    }
}

// ---------------- K6a: chunk scan pass1 — smem-shared B chunk ---------------
__global__ void scan_p1_kernel(const float* __restrict__ Alog) {
    __shared__ float sB[CHLEN][16];
    int b  = blockIdx.z;
    int ch = blockIdx.y;
    int g  = threadIdx.x >> 4;
    int nl = threadIdx.x & 15;
    int d0 = blockIdx.x * 128;
    int base = b * LSEQ + ch * CHLEN;

    {
        int t = threadIdx.x;
        float4 v = *(const float4*)&g_Bm[((size_t)base) * 16 + t * 4];
        *(float4*)&sB[(t * 4) >> 4][(t * 4) & 15] = v;
    }
    __syncthreads();

    for (int dt = 0; dt < 8; dt++) {
        int d = d0 + dt * 16 + g;
        float Adn = -__expf(Alog[d * DSTATE + nl]);
        float P = 1.f, q = 0.f;
        const float* drow  = g_delta + (size_t)d * NT + base;
        const float* xcrow = g_xc    + (size_t)d * NT + base;
        #pragma unroll 4
        for (int l = 0; l < CHLEN; l++) {
            float delta = drow[l];
            float dA = __expf(delta * Adn);
            q = fmaf(dA, q, delta * sB[l][nl] * xcrow[l]);
            P *= dA;
        }
        size_t idx = ((size_t)(b * NCHUNK + ch) * DIN + d) * 16 + nl;
        g_P[idx] = P;
        g_q[idx] = q;
    }
}

// ---------------- K6b: prefix over chunks -> h0 -----------------------------
__global__ void scan_p2_kernel() {
    int idx = blockIdx.x * 256 + threadIdx.x;
    int n = idx & 15;
    int d = (idx >> 4) & (DIN - 1);
    int b = idx >> 13;
    float h = 0.f;
    #pragma unroll
    for (int ch = 0; ch < NCHUNK; ch++) {
        size_t p = ((size_t)(b * NCHUNK + ch) * DIN + d) * 16 + n;
        g_h0[p] = h;
        h = fmaf(g_P[p], h, g_q[p]);
    }
}

// ---------------- K6c: replay + y + gating — smem-shared B/C chunks ---------
__global__ void scan_p3_kernel(const float* __restrict__ Alog,
                               const float* __restrict__ Dp) {
    __shared__ float sB[CHLEN][16];
    __shared__ float sC[CHLEN][16];
    int b  = blockIdx.z;
    int ch = blockIdx.y;
    int g  = threadIdx.x >> 4;
    int nl = threadIdx.x & 15;
    int d0 = blockIdx.x * 128;
    int base = b * LSEQ + ch * CHLEN;

    {
        int t = threadIdx.x;
        float4 v = *(const float4*)&g_Bm[((size_t)base) * 16 + t * 4];
        *(float4*)&sB[(t * 4) >> 4][(t * 4) & 15] = v;
        float4 w = *(const float4*)&g_Cm[((size_t)base) * 16 + t * 4];
        *(float4*)&sC[(t * 4) >> 4][(t * 4) & 15] = w;
    }
    __syncthreads();

    for (int dt = 0; dt < 8; dt++) {
        int d = d0 + dt * 16 + g;
        float Adn = -__expf(Alog[d * DSTATE + nl]);
        float Dd  = Dp[d];
        float h = g_h0[((size_t)(b * NCHUNK + ch) * DIN + d) * 16 + nl];
        const float* drow  = g_delta + (size_t)d * NT + base;
        const float* xcrow = g_xc    + (size_t)d * NT + base;
        const float* zrow  = g_xz + (size_t)(DIN + d) * NT + base;
        #pragma unroll 4
        for (int l = 0; l < CHLEN; l++) {
            float delta = drow[l];
            float xcv = xcrow[l];
            float dA = __expf(delta * Adn);
            h = fmaf(dA, h, delta * sB[l][nl] * xcv);
            float yv = h * sC[l][nl];
            yv += __shfl_xor_sync(0xffffffffu, yv, 1);
            yv += __shfl_xor_sync(0xffffffffu, yv, 2);
            yv += __shfl_xor_sync(0xffffffffu, yv, 4);
            yv += __shfl_xor_sync(0xffffffffu, yv, 8);
            if (nl == 0) {
                float zl = zrow[l];
                float silu = zl / (1.f + __expf(-zl));
                g_y[(size_t)(base + l) * DIN + d] = (yv + Dd * xcv) * silu;
            }
        }
    }
}

// ---------------- K7: residual + output LayerNorm, write (B,C,L,1) ----------
__global__ void ln_out_kernel(const float* __restrict__ x,
                              const float* __restrict__ w,
                              const float* __restrict__ bias,
                              float* __restrict__ out) {
    int b  = blockIdx.y;
    int lx = threadIdx.x;
    int ty = threadIdx.y;
    int l  = blockIdx.x * 32 + lx;
    __shared__ float sS[8][32], sQ[8][32], sMean[32], sR[32];

    const float* xb = x + (size_t)b * CDIM * LSEQ + l;
    const float* ob = g_op + (size_t)b * LSEQ + l;
    float s = 0.f, q = 0.f;
    for (int c = ty; c < CDIM; c += 8) {
        float v = ob[(size_t)c * NT] + xb[(size_t)c * LSEQ];
        s += v; q += v * v;
    }
    sS[ty][lx] = s; sQ[ty][lx] = q;
    __syncthreads();
    if (ty == 0) {
        float ts = 0.f, tq = 0.f;
        #pragma unroll
        for (int i = 0; i < 8; i++) { ts += sS[i][lx]; tq += sQ[i][lx]; }
        float m   = ts * (1.f / CDIM);
        float var = tq * (1.f / CDIM) - m * m;
        sMean[lx] = m;
        sR[lx]    = rsqrtf(var + 1e-5f);
    }
    __syncthreads();
    float m = sMean[lx], r = sR[lx];
    float* outb = out + (size_t)b * CDIM * LSEQ + l;
    for (int c = ty; c < CDIM; c += 8) {
        float v = ob[(size_t)c * NT] + xb[(size_t)c * LSEQ];
        outb[(size_t)c * LSEQ] = (v - m) * r * w[c] + bias[c];
    }
}

// ---------------- launch -----------------------------------------------------
extern "C" void kernel_launch(void* const* d_in, const int* in_sizes, int n_in,
                              void* d_out, int out_size) {
    const float* x         = (const float*)d_in[0];
    const float* ln_w      = (const float*)d_in[1];
    const float* ln_b      = (const float*)d_in[2];
    const float* in_proj_w = (const float*)d_in[3];
    const float* conv_w    = (const float*)d_in[4];
    const float* conv_b    = (const float*)d_in[5];
    const float* x_proj_w  = (const float*)d_in[6];
    const float* dt_proj_w = (const float*)d_in[7];
    const float* dt_proj_b = (const float*)d_in[8];
    const float* A_log     = (const float*)d_in[9];
    const float* Dv        = (const float*)d_in[10];
    const float* out_proj_w= (const float*)d_in[11];
    float* out = (float*)d_out;

    float *p_u, *p_xz, *p_y, *p_op;
    cudaGetSymbolAddress((void**)&p_u,  g_u);
    cudaGetSymbolAddress((void**)&p_xz, g_xz);
    cudaGetSymbolAddress((void**)&p_y,  g_y);
    cudaGetSymbolAddress((void**)&p_op, g_op);

    ln_in_kernel<<<dim3(LSEQ / 32, BATCH), 256>>>(x, ln_w, ln_b);

    // in_proj: (1024,256) @ (8192,256)^T
    gemm_tc_kernel<<<dim3(NT / 64, (2 * DIN) / 128), 256>>>(
        in_proj_w, p_u, p_xz, 2 * DIN, NT, CDIM);

    conv_kernel<<<dim3(NT / 256, DIN), 256>>>(conv_w, conv_b);

    xproj_part_kernel<<<dim3(NT / 64, 4), 256>>>(x_proj_w);
    xred_kernel<<<(48 * NT) / 256, 256>>>();

    delta_kernel<<<dim3(NT / 256, 4), 256>>>(dt_proj_w, dt_proj_b);

    scan_p1_kernel<<<dim3(4, NCHUNK, BATCH), 256>>>(A_log);
    scan_p2_kernel<<<dim3(BATCH * DIN * 16 / 256), 256>>>();
    scan_p3_kernel<<<dim3(4, NCHUNK, BATCH), 256>>>(A_log, Dv);

    // out_proj: (256,512) @ (8192,512)^T
    gemm_tc_kernel<<<dim3(NT / 64, CDIM / 128), 256>>>(
        out_proj_w, p_y, p_op, CDIM, NT, DIN);

    ln_out_kernel<<<dim3(LSEQ / 32, BATCH), dim3(32, 8)>>>(x, ln_w, ln_b, out);
}